// round 1
// baseline (speedup 1.0000x reference)
#include <cuda_runtime.h>
#include <math.h>

#define NN 100000
#define EE 1200000
#define AA 256
#define HH 64
#define TT 4
#define BB 64
#define NSTEPS 6

// ---------------- scratch (device globals; no runtime allocation) ------------
__device__ float g_h[NN * HH];                 // 25.6 MB
__device__ float g_h0[NN * HH];                // 25.6 MB
__device__ float g_tr[(size_t)NN * 256];       // 102.4 MB  transformed, layout [n][t*64+k]
__device__ float g_a[NN * HH];                 // 25.6 MB
__device__ float g_gi[(size_t)NN * 192];       // 76.8 MB
__device__ float g_gh[(size_t)NN * 192];       // 76.8 MB
__device__ float g_Wedge[64 * 256];            // packed edge weights [h][t*64+k]
__device__ float g_WiT[64 * 192];              // gru_Wi transposed  [k][r]
__device__ float g_WhT[64 * 192];              // gru_Wh transposed  [k][r]
__device__ float g_gate[NN];
__device__ float g_gmax[BB];
__device__ float g_den[BB];
__device__ float g_rsum[BB * 128];

// ---------------- generic 64-wide register-blocked GEMM ----------------------
// C[n][c] = sum_k A[n][k] * W[k][c] (+ bias[c]);  64 rows x 64 cols per block,
// 4x4 register tile per thread, K consumed in 64-chunks.
__global__ __launch_bounds__(256) void gemm64(
    const float* __restrict__ A, int lda, int kch,
    const float* __restrict__ W, int ldw,
    const float* __restrict__ bias,
    float* __restrict__ C, float* __restrict__ C2, int ldc,
    int nrows)
{
    __shared__ float sA[64][64];
    __shared__ float sW[64][64];
    const int tid = threadIdx.x;
    const int tx = tid & 15;      // 16 col-groups of 4
    const int ty = tid >> 4;      // 16 row-groups of 4
    const int n0 = blockIdx.x * 64;
    const int c0 = blockIdx.y * 64;

    float acc[4][4] = {};
    for (int kc = 0; kc < kch; ++kc) {
        const int k0 = kc * 64;
#pragma unroll
        for (int i = 0; i < 16; ++i) {
            int idx = tid + i * 256;
            int r = idx >> 6, k = idx & 63;
            int n = n0 + r;
            sA[r][k] = (n < nrows) ? A[(size_t)n * lda + k0 + k] : 0.0f;
        }
#pragma unroll
        for (int i = 0; i < 16; ++i) {
            int idx = tid + i * 256;
            int k = idx >> 6, c = idx & 63;
            sW[k][c] = W[(size_t)(k0 + k) * ldw + c0 + c];
        }
        __syncthreads();
#pragma unroll 16
        for (int kk = 0; kk < 64; ++kk) {
            float4 wv = *(const float4*)&sW[kk][tx << 2];
            float a0 = sA[(ty << 2) + 0][kk];
            float a1 = sA[(ty << 2) + 1][kk];
            float a2 = sA[(ty << 2) + 2][kk];
            float a3 = sA[(ty << 2) + 3][kk];
            acc[0][0] += a0 * wv.x; acc[0][1] += a0 * wv.y; acc[0][2] += a0 * wv.z; acc[0][3] += a0 * wv.w;
            acc[1][0] += a1 * wv.x; acc[1][1] += a1 * wv.y; acc[1][2] += a1 * wv.z; acc[1][3] += a1 * wv.w;
            acc[2][0] += a2 * wv.x; acc[2][1] += a2 * wv.y; acc[2][2] += a2 * wv.z; acc[2][3] += a2 * wv.w;
            acc[3][0] += a3 * wv.x; acc[3][1] += a3 * wv.y; acc[3][2] += a3 * wv.z; acc[3][3] += a3 * wv.w;
        }
        __syncthreads();
    }

    float4 bv = make_float4(0.f, 0.f, 0.f, 0.f);
    if (bias) bv = *(const float4*)&bias[c0 + (tx << 2)];
#pragma unroll
    for (int r = 0; r < 4; ++r) {
        int n = n0 + (ty << 2) + r;
        if (n < nrows) {
            float4 v = make_float4(acc[r][0] + bv.x, acc[r][1] + bv.y,
                                   acc[r][2] + bv.z, acc[r][3] + bv.w);
            size_t o = (size_t)n * ldc + c0 + (tx << 2);
            *(float4*)&C[o] = v;
            if (C2) *(float4*)&C2[o] = v;
        }
    }
}

// ---------------- weight packing (once per launch) ----------------------------
__global__ void pack_weights(const float* __restrict__ edge_W,
                             const float* __restrict__ Wi,
                             const float* __restrict__ Wh)
{
    int i = blockIdx.x * blockDim.x + threadIdx.x;
    if (i < 64 * 256) {
        int h = i >> 8, rest = i & 255;
        int t = rest >> 6, c = rest & 63;
        g_Wedge[i] = edge_W[t * 4096 + h * 64 + c];
    }
    int i2 = i - 64 * 256;
    if (i2 >= 0 && i2 < 64 * 192) {
        int k = i2 / 192, r = i2 % 192;
        g_WiT[i2] = Wi[r * 64 + k];
    }
    int i3 = i2 - 64 * 192;
    if (i3 >= 0 && i3 < 64 * 192) {
        int k = i3 / 192, r = i3 % 192;
        g_WhT[i3] = Wh[r * 64 + k];
    }
}

// ---------------- zero the aggregation buffer ---------------------------------
__global__ void zero_a_kernel()
{
    int i = blockIdx.x * blockDim.x + threadIdx.x;   // over NN*HH/4
    if (i < NN * HH / 4) ((float4*)g_a)[i] = make_float4(0.f, 0.f, 0.f, 0.f);
}

// ---------------- edge gather + scatter-add -----------------------------------
// half-warp per edge: 16 lanes x float4 = 64 floats
__global__ __launch_bounds__(256) void scatter_edges(
    const int* __restrict__ src, const int* __restrict__ dst,
    const int* __restrict__ ety)
{
    int gtid = blockIdx.x * blockDim.x + threadIdx.x;
    int e = gtid >> 4;
    if (e >= EE) return;
    int f = (gtid & 15) << 2;
    int s = src[e], d = dst[e], t = ety[e];
    float4 v = *(const float4*)&g_tr[(size_t)s * 256 + t * 64 + f];
    float* ap = &g_a[(size_t)d * 64 + f];
    atomicAdd(ap + 0, v.x);
    atomicAdd(ap + 1, v.y);
    atomicAdd(ap + 2, v.z);
    atomicAdd(ap + 3, v.w);
}

// ---------------- GRU elementwise ----------------------------------------------
__global__ void gru_ew()
{
    int i = blockIdx.x * blockDim.x + threadIdx.x;
    if (i >= NN * HH) return;
    int n = i >> 6, j = i & 63;
    const float* gin = g_gi + (size_t)n * 192;
    const float* ghn = g_gh + (size_t)n * 192;
    float ir = gin[j], iz = gin[64 + j], in_ = gin[128 + j];
    float hr = ghn[j], hz = ghn[64 + j], hn = ghn[128 + j];
    float r = 1.f / (1.f + expf(-(ir + hr)));
    float z = 1.f / (1.f + expf(-(iz + hz)));
    float nv = tanhf(in_ + r * hn);
    g_h[i] = (1.f - z) * nv + z * g_h[i];
}

// ---------------- attention pooling --------------------------------------------
__device__ void atomicMaxFloat(float* addr, float v)
{
    int* ia = (int*)addr;
    int old = *ia;
    while (true) {
        float f = __int_as_float(old);
        if (f >= v) break;
        int assumed = old;
        old = atomicCAS(ia, assumed, __float_as_int(v));
        if (old == assumed) break;
    }
}

__global__ void init_pool()
{
    int tid = threadIdx.x;
    if (tid < BB) {
        g_gmax[tid] = __int_as_float(0xff800000);   // -inf
        g_den[tid] = 0.f;
    }
    for (int i = tid; i < BB * 128; i += 256) g_rsum[i] = 0.f;
}

// warp per node: gate score + segment max
__global__ __launch_bounds__(256) void gate_kernel(
    const int* __restrict__ gid, const float* __restrict__ gW,
    const float* __restrict__ gb)
{
    int gtid = blockIdx.x * blockDim.x + threadIdx.x;
    int n = gtid >> 5;
    if (n >= NN) return;
    int lane = gtid & 31;
    int j0 = lane << 2;
    float4 fv = (j0 < 64) ? *(const float4*)&g_h[(size_t)n * 64 + j0]
                          : *(const float4*)&g_h0[(size_t)n * 64 + j0 - 64];
    float4 wv = *(const float4*)&gW[j0];
    float s = fv.x * wv.x + fv.y * wv.y + fv.z * wv.z + fv.w * wv.w;
#pragma unroll
    for (int o = 16; o; o >>= 1) s += __shfl_xor_sync(0xffffffffu, s, o);
    if (lane == 0) {
        float g = s + gb[0];
        g_gate[n] = g;
        atomicMaxFloat(&g_gmax[gid[n]], g);
    }
}

// warp per node: e = exp(gate-gmax); accumulate denom and e*feat
__global__ __launch_bounds__(256) void pool_kernel(const int* __restrict__ gid)
{
    int gtid = blockIdx.x * blockDim.x + threadIdx.x;
    int n = gtid >> 5;
    if (n >= NN) return;
    int lane = gtid & 31;
    int g = gid[n];
    float gm = g_gmax[g];
    if (!isfinite(gm)) gm = 0.f;
    float e = expf(g_gate[n] - gm);
    int j0 = lane << 2;
    float4 fv = (j0 < 64) ? *(const float4*)&g_h[(size_t)n * 64 + j0]
                          : *(const float4*)&g_h0[(size_t)n * 64 + j0 - 64];
    float* rp = &g_rsum[g * 128 + j0];
    atomicAdd(rp + 0, e * fv.x);
    atomicAdd(rp + 1, e * fv.y);
    atomicAdd(rp + 2, e * fv.z);
    atomicAdd(rp + 3, e * fv.w);
    if (lane == 0) atomicAdd(&g_den[g], e);
}

// one block per graph: readout / denom -> logits
__global__ void out_kernel(const float* __restrict__ oW,
                           const float* __restrict__ ob,
                           float* __restrict__ out)
{
    int b = blockIdx.x, tid = threadIdx.x;   // 128 threads
    float dn = g_den[b];
    float inv = (dn > 0.f) ? (1.f / dn) : 0.f;
    float r = g_rsum[b * 128 + tid] * inv;
    float p0 = r * oW[tid * 2 + 0];
    float p1 = r * oW[tid * 2 + 1];
#pragma unroll
    for (int o = 16; o; o >>= 1) {
        p0 += __shfl_xor_sync(0xffffffffu, p0, o);
        p1 += __shfl_xor_sync(0xffffffffu, p1, o);
    }
    __shared__ float s0[4], s1[4];
    if ((tid & 31) == 0) { s0[tid >> 5] = p0; s1[tid >> 5] = p1; }
    __syncthreads();
    if (tid == 0) {
        out[b * 2 + 0] = s0[0] + s0[1] + s0[2] + s0[3] + ob[0];
        out[b * 2 + 1] = s1[0] + s1[1] + s1[2] + s1[3] + ob[1];
    }
}

// ---------------- host orchestration --------------------------------------------
extern "C" void kernel_launch(void* const* d_in, const int* in_sizes, int n_in,
                              void* d_out, int out_size)
{
    const float* ann      = (const float*)d_in[0];
    const int*   src      = (const int*)d_in[1];
    const int*   dst      = (const int*)d_in[2];
    const int*   ety      = (const int*)d_in[3];
    const int*   gid      = (const int*)d_in[4];
    const float* reduce_W = (const float*)d_in[5];
    const float* reduce_b = (const float*)d_in[6];
    const float* edge_W   = (const float*)d_in[7];
    const float* edge_b   = (const float*)d_in[8];
    const float* gru_Wi   = (const float*)d_in[9];
    const float* gru_bi   = (const float*)d_in[10];
    const float* gru_Wh   = (const float*)d_in[11];
    const float* gru_bh   = (const float*)d_in[12];
    const float* gate_W   = (const float*)d_in[13];
    const float* gate_b   = (const float*)d_in[14];
    const float* out_W    = (const float*)d_in[15];
    const float* out_b    = (const float*)d_in[16];
    float* out = (float*)d_out;

    float *ph, *ph0, *ptr, *pa, *pgi, *pgh, *pWe, *pWiT, *pWhT;
    cudaGetSymbolAddress((void**)&ph,   g_h);
    cudaGetSymbolAddress((void**)&ph0,  g_h0);
    cudaGetSymbolAddress((void**)&ptr,  g_tr);
    cudaGetSymbolAddress((void**)&pa,   g_a);
    cudaGetSymbolAddress((void**)&pgi,  g_gi);
    cudaGetSymbolAddress((void**)&pgh,  g_gh);
    cudaGetSymbolAddress((void**)&pWe,  g_Wedge);
    cudaGetSymbolAddress((void**)&pWiT, g_WiT);
    cudaGetSymbolAddress((void**)&pWhT, g_WhT);

    const int GB = (NN + 63) / 64;   // 1563

    // h0 = annotation @ reduce_W + reduce_b  (also copy into h)
    gemm64<<<dim3(GB, 1), 256>>>(ann, AA, AA / 64, reduce_W, HH, reduce_b,
                                 ph0, ph, HH, NN);
    pack_weights<<<160, 256>>>(edge_W, gru_Wi, gru_Wh);
    init_pool<<<1, 256>>>();

    for (int s = 0; s < NSTEPS; ++s) {
        // transformed[n][t*64+k] = h @ Wedge + edge_b
        gemm64<<<dim3(GB, 4), 256>>>(ph, HH, 1, pWe, 256, edge_b,
                                     ptr, nullptr, 256, NN);
        zero_a_kernel<<<(NN * HH / 4 + 255) / 256, 256>>>();
        scatter_edges<<<EE * 16 / 256, 256>>>(src, dst, ety);
        // gi = a @ WiT + bi ; gh = h @ WhT + bh
        gemm64<<<dim3(GB, 3), 256>>>(pa, HH, 1, pWiT, 192, gru_bi,
                                     pgi, nullptr, 192, NN);
        gemm64<<<dim3(GB, 3), 256>>>(ph, HH, 1, pWhT, 192, gru_bh,
                                     pgh, nullptr, 192, NN);
        gru_ew<<<(NN * HH + 255) / 256, 256>>>();
    }

    gate_kernel<<<(NN * 32 + 255) / 256, 256>>>(gid, gate_W, gate_b);
    pool_kernel<<<(NN * 32 + 255) / 256, 256>>>(gid);
    out_kernel<<<BB, 128>>>(out_W, out_b, out);
}